// round 6
// baseline (speedup 1.0000x reference)
#include <cuda_runtime.h>
#include <cuda_bf16.h>
#include <cstdint>

// SumPooling / segment_sum with SORTED index (int32 or int64 — auto-detected).
// x: [N, 128] f32, index: [N], out: [16384, 128] f32.
//
// Each warp owns a contiguous range of ROWS_PER_WARP rows. Lane l accumulates
// feature columns [4l, 4l+4) in a float4 register. Sorted index => flush via
// atomicAdd only on segment change (~61 rows/run => ~2-3 flushes per range).
// Purely HBM-bandwidth-bound (512 MB stream).

#define D_FEAT        128
#define N_SEGMENTS    16384
#define WARPS_PER_CTA 8
#define THREADS_PER_CTA (WARPS_PER_CTA * 32)
#define ROWS_PER_WARP 128

__device__ int g_idx_is64;

// JAX with x64 disabled silently downgrades int64 -> int32. Detect on device:
// read element n/2-1 as int64. True int64 buffer -> valid value in [0,16384).
// int32 buffer -> that read aliases the last two sorted int32 values
// (~16383 | ~16383<<32) -> huge -> classify int32.
__global__ void detect_idx_dtype(const void* __restrict__ idx, int n)
{
    const long long* p64 = (const long long*)idx;
    long long probe = p64[(n >> 1) - 1];
    g_idx_is64 = (probe >= 0 && probe < N_SEGMENTS) ? 1 : 0;
}

template <bool IS64>
__device__ __forceinline__ long long load_seg(const void* __restrict__ idx, long long i)
{
    if (IS64) return __ldg((const long long*)idx + i);
    else      return (long long)__ldg((const int*)idx + i);
}

__device__ __forceinline__ void flush(float* __restrict__ out, long long cur,
                                      int lane, float4 acc)
{
    if (cur < 0 || cur >= N_SEGMENTS) return;   // seatbelt only
    float* o = out + cur * D_FEAT + lane * 4;
    atomicAdd(o + 0, acc.x);
    atomicAdd(o + 1, acc.y);
    atomicAdd(o + 2, acc.z);
    atomicAdd(o + 3, acc.w);
}

template <bool IS64>
__device__ __forceinline__ void segsum_body(const float* __restrict__ x,
                                            const void* __restrict__ index,
                                            float* __restrict__ out,
                                            int n_rows)
{
    const int warp_global = blockIdx.x * WARPS_PER_CTA + (threadIdx.x >> 5);
    const int lane = threadIdx.x & 31;

    long long r0 = (long long)warp_global * ROWS_PER_WARP;
    if (r0 >= n_rows) return;
    long long r1 = r0 + ROWS_PER_WARP;
    if (r1 > n_rows) r1 = n_rows;

    const float4* __restrict__ x4 = reinterpret_cast<const float4*>(x);

    float4 acc = make_float4(0.f, 0.f, 0.f, 0.f);
    long long cur = load_seg<IS64>(index, r0);

    long long r = r0;
    for (; r + 4 <= r1; r += 4) {
        long long s0 = load_seg<IS64>(index, r + 0);
        long long s1 = load_seg<IS64>(index, r + 1);
        long long s2 = load_seg<IS64>(index, r + 2);
        long long s3 = load_seg<IS64>(index, r + 3);
        float4 v0 = __ldg(x4 + (r + 0) * 32 + lane);
        float4 v1 = __ldg(x4 + (r + 1) * 32 + lane);
        float4 v2 = __ldg(x4 + (r + 2) * 32 + lane);
        float4 v3 = __ldg(x4 + (r + 3) * 32 + lane);

        if (s0 == cur && s3 == cur) {
            // Fast path: all four rows in the current run.
            acc.x += v0.x + v1.x + v2.x + v3.x;
            acc.y += v0.y + v1.y + v2.y + v3.y;
            acc.z += v0.z + v1.z + v2.z + v3.z;
            acc.w += v0.w + v1.w + v2.w + v3.w;
        } else {
            long long segs[4] = {s0, s1, s2, s3};
            float4    vals[4] = {v0, v1, v2, v3};
            #pragma unroll
            for (int k = 0; k < 4; ++k) {
                if (segs[k] != cur) {
                    flush(out, cur, lane, acc);
                    acc = make_float4(0.f, 0.f, 0.f, 0.f);
                    cur = segs[k];
                }
                acc.x += vals[k].x;
                acc.y += vals[k].y;
                acc.z += vals[k].z;
                acc.w += vals[k].w;
            }
        }
    }
    for (; r < r1; ++r) {
        long long s = load_seg<IS64>(index, r);
        float4 v = __ldg(x4 + r * 32 + lane);
        if (s != cur) {
            flush(out, cur, lane, acc);
            acc = make_float4(0.f, 0.f, 0.f, 0.f);
            cur = s;
        }
        acc.x += v.x;
        acc.y += v.y;
        acc.z += v.z;
        acc.w += v.w;
    }
    flush(out, cur, lane, acc);
}

__global__ __launch_bounds__(THREADS_PER_CTA)
void segsum_sorted_kernel(const float* __restrict__ x,
                          const void* __restrict__ index,
                          float* __restrict__ out,
                          int n_rows)
{
    if (g_idx_is64) segsum_body<true >(x, index, out, n_rows);
    else            segsum_body<false>(x, index, out, n_rows);
}

extern "C" void kernel_launch(void* const* d_in, const int* in_sizes, int n_in,
                              void* d_out, int out_size)
{
    const float* x     = (const float*)d_in[0];
    const void*  index = d_in[1];
    float*       out   = (float*)d_out;

    const int n_rows = in_sizes[0] / D_FEAT;   // 1,000,000

    // Output is poisoned by the harness; segment sum needs zero init.
    cudaMemsetAsync(d_out, 0, (size_t)out_size * sizeof(float));

    detect_idx_dtype<<<1, 1>>>(index, in_sizes[1]);

    const int warps  = (n_rows + ROWS_PER_WARP - 1) / ROWS_PER_WARP;
    const int blocks = (warps + WARPS_PER_CTA - 1) / WARPS_PER_CTA;

    segsum_sorted_kernel<<<blocks, THREADS_PER_CTA>>>(x, index, out, n_rows);
}

// round 8
// speedup vs baseline: 1.1147x; 1.1147x over previous
#include <cuda_runtime.h>
#include <cuda_bf16.h>
#include <cstdint>

// SumPooling / segment_sum with SORTED index (int32 or int64 — auto-detected).
// x: [N, 128] f32, index: [N] sorted, out: [16384, 128] f32.
//
// Two-kernel plan, no memset, no atomics:
//   K1: one coalesced pass over index -> g_start[s] = lower_bound(index, s).
//       (scatter of exactly 16385 ints total; empty segments handled.)
//   K2: one CTA per segment. 8 warps stream the segment's contiguous rows
//       (float4 per lane), smem cross-warp reduce, single plain coalesced
//       512B store per segment (writes zeros for empty segments).
// Purely HBM-bound: 512MB x read + 8MB out write + 4MB index.

#define D_FEAT      128
#define N_SEGMENTS  16384

__device__ int g_start[N_SEGMENTS + 1];

// JAX with x64 disabled silently downgrades int64 -> int32. Probe: read the
// middle of the buffer as int64. True int64 -> small value in [0,16384).
// int32 -> aliases two packed sorted int32s near the end -> huge.
__device__ __forceinline__ bool idx_is64(const void* __restrict__ idx, int n)
{
    long long probe = __ldg((const long long*)idx + ((n >> 1) - 1));
    return (probe >= 0 && probe < N_SEGMENTS);
}

template <bool IS64>
__device__ __forceinline__ int load_seg(const void* __restrict__ idx, int i)
{
    if (IS64) return (int)__ldg((const long long*)idx + i);
    else      return __ldg((const int*)idx + i);
}

template <bool IS64>
__device__ __forceinline__ void boundaries_body(const void* __restrict__ index, int n)
{
    int i = blockIdx.x * blockDim.x + threadIdx.x;
    if (i >= n) return;

    int curr = load_seg<IS64>(index, i);
    int prev = (i == 0) ? -1 : load_seg<IS64>(index, i - 1);

    // start[s] = i for all s in (prev, curr]
    for (int s = prev + 1; s <= curr; ++s) g_start[s] = i;

    if (i == n - 1) {
        // start[s] = n for all s in (curr, N_SEGMENTS]
        for (int s = curr + 1; s <= N_SEGMENTS; ++s) g_start[s] = n;
    }
}

__global__ __launch_bounds__(256)
void seg_boundaries_kernel(const void* __restrict__ index, int n)
{
    if (idx_is64(index, n)) boundaries_body<true >(index, n);
    else                    boundaries_body<false>(index, n);
}

#define WARPS 8

__global__ __launch_bounds__(WARPS * 32)
void segsum_kernel(const float* __restrict__ x, float* __restrict__ out)
{
    __shared__ float4 red[WARPS][32];

    const int seg  = blockIdx.x;
    const int w    = threadIdx.x >> 5;
    const int lane = threadIdx.x & 31;

    const int s0 = g_start[seg];
    const int s1 = g_start[seg + 1];

    const float4* __restrict__ x4 = reinterpret_cast<const float4*>(x);

    // Warp w handles rows s0+w, s0+w+8, ... Two accumulators for MLP.
    float4 a0 = make_float4(0.f, 0.f, 0.f, 0.f);
    float4 a1 = make_float4(0.f, 0.f, 0.f, 0.f);

    int r = s0 + w;
    for (; r + WARPS < s1; r += 2 * WARPS) {
        float4 v0 = __ldg(x4 + (long long)r * 32 + lane);
        float4 v1 = __ldg(x4 + (long long)(r + WARPS) * 32 + lane);
        a0.x += v0.x; a0.y += v0.y; a0.z += v0.z; a0.w += v0.w;
        a1.x += v1.x; a1.y += v1.y; a1.z += v1.z; a1.w += v1.w;
    }
    if (r < s1) {
        float4 v0 = __ldg(x4 + (long long)r * 32 + lane);
        a0.x += v0.x; a0.y += v0.y; a0.z += v0.z; a0.w += v0.w;
    }
    a0.x += a1.x; a0.y += a1.y; a0.z += a1.z; a0.w += a1.w;

    red[w][lane] = a0;
    __syncthreads();

    // Threads 0..127: thread t reduces one float4-column-group across warps?
    // Simpler: lanes of warps 0..3 each own one of the 128 float columns.
    if (threadIdx.x < 128) {
        const int t = threadIdx.x;         // column group owner: col4 = t % 32, pick component by t/32
        // Reduce across the 8 warps for float4 group (t & 31), then this
        // thread extracts component (t >> 5).
        float4 s = red[0][t & 31];
        #pragma unroll
        for (int ww = 1; ww < WARPS; ++ww) {
            float4 v = red[ww][t & 31];
            s.x += v.x; s.y += v.y; s.z += v.z; s.w += v.w;
        }
        float val = (t >> 5) == 0 ? s.x : (t >> 5) == 1 ? s.y : (t >> 5) == 2 ? s.z : s.w;
        // Column index: group (t&31) covers columns [4*(t&31), 4*(t&31)+4),
        // component (t>>5) selects within the group.
        out[(long long)seg * D_FEAT + 4 * (t & 31) + (t >> 5)] = val;
    }
}

extern "C" void kernel_launch(void* const* d_in, const int* in_sizes, int n_in,
                              void* d_out, int out_size)
{
    const float* x     = (const float*)d_in[0];
    const void*  index = d_in[1];
    float*       out   = (float*)d_out;

    const int n_rows = in_sizes[0] / D_FEAT;   // 1,000,000

    seg_boundaries_kernel<<<(n_rows + 255) / 256, 256>>>(index, n_rows);
    segsum_kernel<<<N_SEGMENTS, WARPS * 32>>>(x, out);
}